// round 8
// baseline (speedup 1.0000x reference)
#include <cuda_runtime.h>
#include <cuda_fp16.h>
#include <cuda_bf16.h>
#include <cstdint>

#define N_MAX 100000
#define E_MAX 1600000
#define T_MAX (E_MAX + N_MAX)
#define SCAN_B 1024
#define NBLK_SCAN_MAX 128

// scratch (device globals: allocation-free)
__device__ __half g_h1h[N_MAX * 64];
__device__ float  g_as1[N_MAX * 8];
__device__ float  g_ad1[N_MAX * 8];
__device__ float  g_h2[N_MAX * 16];
__device__ float  g_as2[N_MAX];
__device__ float  g_ad2[N_MAX];
__device__ int    g_src[E_MAX];
__device__ unsigned long long g_dr[E_MAX];  // rank<<32 | dst
__device__ int    g_deg[N_MAX];
__device__ int    g_off[N_MAX + 1];
__device__ int    g_csr[T_MAX];
__device__ int    g_bsum[NBLK_SCAN_MAX];

// ---------------- f32x2 packed helpers ----------------
__device__ __forceinline__ unsigned long long pk2(float a, float b) {
    unsigned long long r;
    asm("mov.b64 %0, {%1, %2};" : "=l"(r) : "f"(a), "f"(b));
    return r;
}
__device__ __forceinline__ void fma2(unsigned long long& d, unsigned long long a,
                                     unsigned long long b) {
    asm("fma.rn.f32x2 %0, %1, %2, %0;" : "+l"(d) : "l"(a), "l"(b));
}
__device__ __forceinline__ float2 up2(unsigned long long v) {
    float2 r;
    asm("mov.b64 {%0, %1}, %2;" : "=f"(r.x), "=f"(r.y) : "l"(v));
    return r;
}

// ------- decode + degree count (deg pre-zeroed by memset); per-block dtype -
__global__ void k_decode_deg(const void* __restrict__ ei, int E) {
    __shared__ int sIs64;
    if (threadIdx.x == 0) {
        // int64 little-endian small values -> odd 32-bit words are all zero
        const unsigned int* w = (const unsigned int*)ei;
        int z = 0;
#pragma unroll
        for (int j = 0; j < 32; j++)
            if (w[2 * j + 1] == 0u) z++;
        sIs64 = (z == 32) ? 1 : 0;
    }
    __syncthreads();
    int e = blockIdx.x * blockDim.x + threadIdx.x;
    if (e >= E) return;
    int s, d;
    if (sIs64) {
        const long long* p = (const long long*)ei;
        s = (int)p[e];
        d = (int)p[e + E];
    } else {
        const int* p = (const int*)ei;
        s = p[e];
        d = p[e + E];
    }
    g_src[e] = s;
    int r = atomicAdd(&g_deg[d], 1);  // rank starting at 0
    g_dr[e] = ((unsigned long long)(unsigned)r << 32) | (unsigned)d;
}

// ---------------- scan over edge degrees (block-local) ----------------
__global__ void k_scan1(int N) {
    __shared__ int wsum[32];
    int i = blockIdx.x * SCAN_B + threadIdx.x;
    int v = (i < N) ? g_deg[i] : 0;
    int lane = threadIdx.x & 31, wid = threadIdx.x >> 5;
    int s = v;
#pragma unroll
    for (int o = 1; o < 32; o <<= 1) {
        int t = __shfl_up_sync(0xffffffffu, s, o);
        if (lane >= o) s += t;
    }
    if (lane == 31) wsum[wid] = s;
    __syncthreads();
    if (wid == 0) {
        int ws = wsum[lane];
#pragma unroll
        for (int o = 1; o < 32; o <<= 1) {
            int t = __shfl_up_sync(0xffffffffu, ws, o);
            if (lane >= o) ws += t;
        }
        wsum[lane] = ws;
    }
    __syncthreads();
    int base = (wid > 0) ? wsum[wid - 1] : 0;
    if (i < N) g_off[i] = base + s - v;  // block-local exclusive
    if (threadIdx.x == 0) g_bsum[blockIdx.x] = wsum[31];
}

// finalize offsets (+i self-loop slots) + self-loop scatter;
// block sums scanned inline per block (nblk <= 128).
__global__ void k_scan3(int nblk, int N) {
    __shared__ int sb[NBLK_SCAN_MAX];
    __shared__ int ws[4];
    int tid = threadIdx.x;
    int lane = tid & 31, w = tid >> 5;
    int v = 0, s = 0;
    if (tid < 128) {
        v = (tid < nblk) ? g_bsum[tid] : 0;
        s = v;
#pragma unroll
        for (int o = 1; o < 32; o <<= 1) {
            int t = __shfl_up_sync(0xffffffffu, s, o);
            if (lane >= o) s += t;
        }
        if (lane == 31) ws[w] = s;
    }
    __syncthreads();
    if (tid < 128) {
        int base = 0;
#pragma unroll
        for (int j = 0; j < 4; j++)
            if (j < w) base += ws[j];
        sb[tid] = base + s - v;  // exclusive
    }
    if (blockIdx.x == 0 && tid == 0)
        g_off[N] = ws[0] + ws[1] + ws[2] + ws[3] + N;  // edges + self loops
    __syncthreads();
    int i = blockIdx.x * blockDim.x + tid;
    if (i < N) {
        int o = g_off[i] + sb[i / SCAN_B] + i;  // +i: one self-loop slot per node
        g_off[i] = o;
        g_csr[o] = i;  // self loop at slot 0
    }
}

// atomic-free scatter using precomputed ranks (slot 0 = self loop)
__global__ void k_scat_edge(int E) {
    int e = blockIdx.x * blockDim.x + threadIdx.x;
    if (e >= E) return;
    unsigned long long dr = g_dr[e];
    int d = (int)(unsigned)dr;
    int r = (int)(dr >> 32);
    g_csr[__ldg(&g_off[d]) + 1 + r] = g_src[e];
}

// ---------------- GEMM1 + fused att dots ----------------------------------
#define SXI(r, kq) ((r) * 128 + ((((kq) ^ ((r) & 7))) << 2))

__global__ void __launch_bounds__(128) k_gemm1(const float* __restrict__ x,
                                               const float* __restrict__ W,
                                               const float* __restrict__ att_s,
                                               const float* __restrict__ att_d,
                                               int N) {
    extern __shared__ float smem[];
    float* sW = smem;           // 128*64
    float* sX = smem + 8192;    // 128*128 swizzled
    float* sAs = smem + 24576;  // 64
    float* sAd = smem + 24640;  // 64
    int tid = threadIdx.x;

    const float4* W4 = (const float4*)W;
    float4* sW4 = (float4*)sW;
#pragma unroll
    for (int i = tid; i < 2048; i += 128) sW4[i] = W4[i];
    if (tid < 64) {
        sAs[tid] = att_s[tid];
        sAd[tid] = att_d[tid];
    }

    int rowbase = blockIdx.x * 128;
    const float4* x4 = (const float4*)x;
#pragma unroll
    for (int idx = tid; idx < 4096; idx += 128) {
        int r = idx >> 5, kq = idx & 31;
        int row = rowbase + r;
        float4 v = make_float4(0.f, 0.f, 0.f, 0.f);
        if (row < N) v = x4[(size_t)row * 32 + kq];
        *(float4*)&sX[SXI(r, kq)] = v;
    }
    __syncthreads();

    int rowthr = tid >> 3;  // 0..15
    int colthr = tid & 7;   // 0..7
    int c0 = colthr * 4;

    unsigned long long acc[8][4];
#pragma unroll
    for (int i = 0; i < 8; i++)
#pragma unroll
        for (int j = 0; j < 4; j++) acc[i][j] = 0ULL;

#pragma unroll 4
    for (int kq = 0; kq < 32; kq++) {
        float4 xq[8];
#pragma unroll
        for (int i = 0; i < 8; i++) xq[i] = *(const float4*)&sX[SXI(rowthr + 16 * i, kq)];
#pragma unroll
        for (int kk = 0; kk < 4; kk++) {
            int k = kq * 4 + kk;
            float4 wa = *(const float4*)&sW[k * 64 + c0];
            float4 wb = *(const float4*)&sW[k * 64 + c0 + 32];
            unsigned long long w0 = pk2(wa.x, wa.y), w1 = pk2(wa.z, wa.w);
            unsigned long long w2 = pk2(wb.x, wb.y), w3 = pk2(wb.z, wb.w);
#pragma unroll
            for (int i = 0; i < 8; i++) {
                float xv = ((const float*)&xq[i])[kk];
                unsigned long long xd = pk2(xv, xv);
                fma2(acc[i][0], xd, w0);
                fma2(acc[i][1], xd, w1);
                fma2(acc[i][2], xd, w2);
                fma2(acc[i][3], xd, w3);
            }
        }
    }

    float as0 = sAs[c0], as1v = sAs[c0 + 1], as2v = sAs[c0 + 2], as3 = sAs[c0 + 3];
    float asH0 = sAs[c0 + 32], asH1 = sAs[c0 + 33], asH2 = sAs[c0 + 34], asH3 = sAs[c0 + 35];
    float ad0 = sAd[c0], ad1v = sAd[c0 + 1], ad2v = sAd[c0 + 2], ad3 = sAd[c0 + 3];
    float adH0 = sAd[c0 + 32], adH1 = sAd[c0 + 33], adH2 = sAd[c0 + 34], adH3 = sAd[c0 + 35];
    int hl = c0 >> 3;  // valid on even lanes

#pragma unroll
    for (int i = 0; i < 8; i++) {
        int row = rowbase + rowthr + 16 * i;
        bool ok = (row < N);
        float2 p0 = up2(acc[i][0]), p1 = up2(acc[i][1]);
        float2 p2 = up2(acc[i][2]), p3 = up2(acc[i][3]);
        if (ok) {
            __half2 h0 = __floats2half2_rn(p0.x, p0.y);
            __half2 h1v = __floats2half2_rn(p1.x, p1.y);
            __half2 h2v = __floats2half2_rn(p2.x, p2.y);
            __half2 h3 = __floats2half2_rn(p3.x, p3.y);
            uint2 u0, u1;
            u0.x = *(unsigned*)&h0;  u0.y = *(unsigned*)&h1v;
            u1.x = *(unsigned*)&h2v; u1.y = *(unsigned*)&h3;
            *(uint2*)&g_h1h[(size_t)row * 64 + c0] = u0;
            *(uint2*)&g_h1h[(size_t)row * 64 + c0 + 32] = u1;
        }
        float sl = p0.x * as0 + p0.y * as1v + p1.x * as2v + p1.y * as3;
        float sh = p2.x * asH0 + p2.y * asH1 + p3.x * asH2 + p3.y * asH3;
        float dl = p0.x * ad0 + p0.y * ad1v + p1.x * ad2v + p1.y * ad3;
        float dh = p2.x * adH0 + p2.y * adH1 + p3.x * adH2 + p3.y * adH3;
        sl += __shfl_xor_sync(0xffffffffu, sl, 1);
        sh += __shfl_xor_sync(0xffffffffu, sh, 1);
        dl += __shfl_xor_sync(0xffffffffu, dl, 1);
        dh += __shfl_xor_sync(0xffffffffu, dh, 1);
        if (ok && !(tid & 1)) {
            g_as1[row * 8 + hl] = sl;
            g_as1[row * 8 + hl + 4] = sh;
            g_ad1[row * 8 + hl] = dl;
            g_ad1[row * 8 + hl + 4] = dh;
        }
    }
}

// ------- aggregate layer 1 + bias + elu + GEMM2 + att2 dots (fused) -------
// warp per node; 2 edge slots x 16 channel lanes; fp16 feature gather.
__global__ void __launch_bounds__(256) k_agg1(const float* __restrict__ b1,
                                              const float* __restrict__ W2,
                                              const float* __restrict__ att_s2,
                                              const float* __restrict__ att_d2,
                                              int N) {
    __shared__ float sW[64 * 16];
    __shared__ float sAs[16], sAd[16], sB[64];
    __shared__ float sH[8][64];
    int tid = threadIdx.x;
    for (int i = tid; i < 1024; i += 256) sW[i] = W2[i];
    if (tid < 16) {
        sAs[tid] = att_s2[tid];
        sAd[tid] = att_d2[tid];
    }
    if (tid < 64) sB[tid] = b1[tid];
    __syncthreads();

    int warp = (blockIdx.x * 256 + tid) >> 5;
    if (warp >= N) return;
    int lane = tid & 31;
    int wib = tid >> 5;
    int sub = lane >> 4;  // edge slot 0/1
    int q = lane & 15;    // channel quad
    int c0 = q * 4;
    int head = q >> 1;
    int n = warp;
    float ad = g_ad1[n * 8 + head];
    int beg = g_off[n], end = g_off[n + 1];
    float a0 = 0.f, a1 = 0.f, a2 = 0.f, a3 = 0.f, den = 0.f;
    for (int e = beg + sub; e < end; e += 2) {
        int src = __ldg(&g_csr[e]);
        float as = __ldg(&g_as1[src * 8 + head]);
        float a = as + ad;
        a = (a > 0.f) ? a : 0.2f * a;
        float ex = __expf(a);
        den += ex;
        uint2 hv = *(const uint2*)&g_h1h[(size_t)src * 64 + c0];
        float2 p0 = __half22float2(*(__half2*)&hv.x);
        float2 p1 = __half22float2(*(__half2*)&hv.y);
        a0 = fmaf(ex, p0.x, a0);
        a1 = fmaf(ex, p0.y, a1);
        a2 = fmaf(ex, p1.x, a2);
        a3 = fmaf(ex, p1.y, a3);
    }
    a0 += __shfl_xor_sync(0xffffffffu, a0, 16);
    a1 += __shfl_xor_sync(0xffffffffu, a1, 16);
    a2 += __shfl_xor_sync(0xffffffffu, a2, 16);
    a3 += __shfl_xor_sync(0xffffffffu, a3, 16);
    den += __shfl_xor_sync(0xffffffffu, den, 16);
    if (sub == 0) {
        float inv = 1.f / (den + 1e-16f);
        float o0 = a0 * inv + sB[c0];
        float o1 = a1 * inv + sB[c0 + 1];
        float o2 = a2 * inv + sB[c0 + 2];
        float o3 = a3 * inv + sB[c0 + 3];
        o0 = (o0 > 0.f) ? o0 : (__expf(o0) - 1.f);  // elu
        o1 = (o1 > 0.f) ? o1 : (__expf(o1) - 1.f);
        o2 = (o2 > 0.f) ? o2 : (__expf(o2) - 1.f);
        o3 = (o3 > 0.f) ? o3 : (__expf(o3) - 1.f);
        *(float4*)&sH[wib][c0] = make_float4(o0, o1, o2, o3);
    }
    __syncwarp();

    // fused layer-2 GEMM (64x16) + att2 dots for this node
    if (lane < 16) {
        int c = lane;
        float acc = 0.f;
#pragma unroll
        for (int k = 0; k < 64; k += 4) {
            float4 h = *(const float4*)&sH[wib][k];
            acc = fmaf(h.x, sW[(k + 0) * 16 + c], acc);
            acc = fmaf(h.y, sW[(k + 1) * 16 + c], acc);
            acc = fmaf(h.z, sW[(k + 2) * 16 + c], acc);
            acc = fmaf(h.w, sW[(k + 3) * 16 + c], acc);
        }
        float p = acc * sAs[c], qd = acc * sAd[c];
#pragma unroll
        for (int o = 8; o >= 1; o >>= 1) {
            p += __shfl_xor_sync(0xffffu, p, o);
            qd += __shfl_xor_sync(0xffffu, qd, o);
        }
        g_h2[n * 16 + c] = acc;
        if (c == 0) {
            g_as2[n] = p;
            g_ad2[n] = qd;
        }
    }
}

// ---------------- aggregate layer 2 + log_softmax: 4 edges x 8 lanes ------
__global__ void k_agg2(const float* __restrict__ b2, float* __restrict__ out,
                       int N) {
    int warp = (blockIdx.x * blockDim.x + threadIdx.x) >> 5;
    if (warp >= N) return;
    int lane = threadIdx.x & 31;
    int sub = lane >> 3;  // 0..3 edge slot
    int cg = lane & 7;
    int c0 = cg * 2;
    int n = warp;
    float ad = g_ad2[n];
    int beg = g_off[n], end = g_off[n + 1];
    float ax = 0.f, ay = 0.f, den = 0.f;
    for (int e = beg + sub; e < end; e += 4) {
        int src = __ldg(&g_csr[e]);
        float as = __ldg(&g_as2[src]);
        float a = as + ad;
        a = (a > 0.f) ? a : 0.2f * a;
        float ex = __expf(a);
        den += ex;
        float2 hv = *(const float2*)&g_h2[src * 16 + c0];
        ax = fmaf(ex, hv.x, ax);
        ay = fmaf(ex, hv.y, ay);
    }
    ax += __shfl_xor_sync(0xffffffffu, ax, 8);
    ax += __shfl_xor_sync(0xffffffffu, ax, 16);
    ay += __shfl_xor_sync(0xffffffffu, ay, 8);
    ay += __shfl_xor_sync(0xffffffffu, ay, 16);
    den += __shfl_xor_sync(0xffffffffu, den, 8);
    den += __shfl_xor_sync(0xffffffffu, den, 16);
    float inv = 1.f / (den + 1e-16f);
    float v0 = ax * inv + b2[c0];
    float v1 = ay * inv + b2[c0 + 1];
    float m = fmaxf(v0, v1);
#pragma unroll
    for (int o = 4; o >= 1; o >>= 1) m = fmaxf(m, __shfl_xor_sync(0xffffffffu, m, o));
    float s = __expf(v0 - m) + __expf(v1 - m);
#pragma unroll
    for (int o = 4; o >= 1; o >>= 1) s += __shfl_xor_sync(0xffffffffu, s, o);
    float ls = __logf(s);
    if (sub == 0) {
        out[n * 16 + c0] = v0 - m - ls;
        out[n * 16 + c0 + 1] = v1 - m - ls;
    }
}

// ---------------------------------------------------------------------------
extern "C" void kernel_launch(void* const* d_in, const int* in_sizes, int n_in,
                              void* d_out, int out_size) {
    const float* x        = (const float*)d_in[0];
    const void*  ei       = d_in[1];
    const float* W1       = (const float*)d_in[2];
    const float* b1       = (const float*)d_in[3];
    const float* att_src1 = (const float*)d_in[4];
    const float* att_dst1 = (const float*)d_in[5];
    const float* W2       = (const float*)d_in[6];
    const float* b2       = (const float*)d_in[7];
    const float* att_src2 = (const float*)d_in[8];
    const float* att_dst2 = (const float*)d_in[9];
    float* out = (float*)d_out;

    int N = in_sizes[0] / 128;
    int E = in_sizes[1] / 2;
    if (N > N_MAX) N = N_MAX;
    if (E > E_MAX) E = E_MAX;

    int gE = (E + 255) / 256;
    int gN = (N + 255) / 256;
    int nblkScan = (N + SCAN_B - 1) / SCAN_B;

    void* degPtr = nullptr;
    cudaGetSymbolAddress(&degPtr, g_deg);
    cudaMemsetAsync(degPtr, 0, (size_t)N * sizeof(int));

    k_decode_deg<<<gE, 256>>>(ei, E);
    k_scan1<<<nblkScan, SCAN_B>>>(N);
    k_scan3<<<gN, 256>>>(nblkScan, N);
    k_scat_edge<<<gE, 256>>>(E);

    (void)cudaFuncSetAttribute(k_gemm1,
                               cudaFuncAttributeMaxDynamicSharedMemorySize, 99328);
    k_gemm1<<<(N + 127) / 128, 128, 99328>>>(x, W1, att_src1, att_dst1, N);
    k_agg1<<<(N * 32 + 255) / 256, 256>>>(b1, W2, att_src2, att_dst2, N);
    k_agg2<<<(N * 32 + 255) / 256, 256>>>(b2, out, N);
}